// round 3
// baseline (speedup 1.0000x reference)
#include <cuda_runtime.h>

#define NQ 10
#define NL 4
#define BATCH 4096
#define FULL 0xFFFFFFFFu

// State layout: global amplitude index idx = (lane << 5) | k, k = 0..31.
// Index bit b (qubit q = 9-b): b in [0,5) -> register bit of k; b in [5,10) -> lane bit (b-5).

// ---- fused RY then RZ on a register bit ----
template<int B>
__device__ __forceinline__ void ryrz_reg(float (&ar)[32], float (&ai)[32],
                                         float cy, float sy, float cz, float sz) {
#pragma unroll
    for (int k0 = 0; k0 < 32; ++k0) {
        if (k0 & (1 << B)) continue;
        const int k1 = k0 | (1 << B);
        float r0 = ar[k0], i0 = ai[k0], r1 = ar[k1], i1 = ai[k1];
        // RY: t0 = cy*a0 - sy*a1 ; t1 = sy*a0 + cy*a1
        float t0r = fmaf(cy, r0, -(sy * r1));
        float t0i = fmaf(cy, i0, -(sy * i1));
        float t1r = fmaf(sy, r0, cy * r1);
        float t1i = fmaf(sy, i0, cy * i1);
        // RZ phases: row0 *= (cz,-sz), row1 *= (cz,+sz)
        ar[k0] = fmaf(cz, t0r,  sz * t0i);
        ai[k0] = fmaf(cz, t0i, -(sz * t0r));
        ar[k1] = fmaf(cz, t1r, -(sz * t1i));
        ai[k1] = fmaf(cz, t1i,  sz * t1r);
    }
}

// ---- fused RY then RZ on a lane bit ----
template<int LB>
__device__ __forceinline__ void ryrz_lane(float (&ar)[32], float (&ai)[32],
                                          float cy, float sy, float cz, float sz, int lane) {
    const int m = 1 << LB;
    const bool hi = (lane & m) != 0;
    const float ss = hi ? sy : -sy;   // row sign for RY partner term
    const float pz = hi ? sz : -sz;   // RZ phase imaginary part
#pragma unroll
    for (int k = 0; k < 32; ++k) {
        float pr = __shfl_xor_sync(FULL, ar[k], m);
        float qi = __shfl_xor_sync(FULL, ai[k], m);
        float tr = fmaf(cy, ar[k], ss * pr);
        float ti = fmaf(cy, ai[k], ss * qi);
        // (cz, pz) * (tr, ti)
        ar[k] = fmaf(cz, tr, -(pz * ti));
        ai[k] = fmaf(cz, ti,  pz * tr);
    }
}

// ---- CNOT variants (control bit BC/LC, target bit BT/LT) ----
template<int BC, int BT>   // both register bits: pure register swaps
__device__ __forceinline__ void cnot_rr(float (&ar)[32], float (&ai)[32]) {
#pragma unroll
    for (int k = 0; k < 32; ++k) {
        if ((k & (1 << BC)) && !(k & (1 << BT))) {
            const int k1 = k | (1 << BT);
            float tr = ar[k]; ar[k] = ar[k1]; ar[k1] = tr;
            float ti = ai[k]; ai[k] = ai[k1]; ai[k1] = ti;
        }
    }
}

template<int LC, int BT>   // control on lane bit, target register bit: predicated swaps
__device__ __forceinline__ void cnot_lr(float (&ar)[32], float (&ai)[32], int lane) {
    if (lane & (1 << LC)) {
#pragma unroll
        for (int k = 0; k < 32; ++k) {
            if (!(k & (1 << BT))) {
                const int k1 = k | (1 << BT);
                float tr = ar[k]; ar[k] = ar[k1]; ar[k1] = tr;
                float ti = ai[k]; ai[k] = ai[k1]; ai[k1] = ti;
            }
        }
    }
}

template<int BC, int LT>   // control register bit, target lane bit: full exchange via shfl_xor
__device__ __forceinline__ void cnot_rl(float (&ar)[32], float (&ai)[32]) {
    const int m = 1 << LT;
#pragma unroll
    for (int k = 0; k < 32; ++k) {
        if (k & (1 << BC)) {
            ar[k] = __shfl_xor_sync(FULL, ar[k], m);
            ai[k] = __shfl_xor_sync(FULL, ai[k], m);
        }
    }
}

template<int LC, int LT>   // both lane bits: indexed shuffle with conditional source
__device__ __forceinline__ void cnot_ll(float (&ar)[32], float (&ai)[32], int lane) {
    const int src = (lane & (1 << LC)) ? (lane ^ (1 << LT)) : lane;
#pragma unroll
    for (int k = 0; k < 32; ++k) {
        ar[k] = __shfl_sync(FULL, ar[k], src);
        ai[k] = __shfl_sync(FULL, ai[k], src);
    }
}

// ---- dispatch helpers (compile-time qubit -> bit mapping) ----
template<int Q>
__device__ __forceinline__ void apply_ryrz(float (&ar)[32], float (&ai)[32],
                                           const float* __restrict__ p, int lane) {
    const float hy = 0.5f * __ldg(p + Q);
    const float hz = 0.5f * __ldg(p + NQ + Q);
    float cy, sy, cz, sz;
    __sincosf(hy, &sy, &cy);
    __sincosf(hz, &sz, &cz);
    constexpr int B = 9 - Q;
    if constexpr (B >= 5) ryrz_lane<B - 5>(ar, ai, cy, sy, cz, sz, lane);
    else                  ryrz_reg<B>(ar, ai, cy, sy, cz, sz);
}

template<int C>
__device__ __forceinline__ void apply_cnot(float (&ar)[32], float (&ai)[32], int lane) {
    constexpr int T  = (C + 1) % NQ;
    constexpr int BC = 9 - C;
    constexpr int BT = 9 - T;
    if constexpr (BC >= 5 && BT >= 5) cnot_ll<BC - 5, BT - 5>(ar, ai, lane);
    else if constexpr (BC >= 5)       cnot_lr<BC - 5, BT>(ar, ai, lane);
    else if constexpr (BT >= 5)       cnot_rl<BC, BT - 5>(ar, ai);
    else                              cnot_rr<BC, BT>(ar, ai);
}

__global__ void __launch_bounds__(256)
pqc_kernel(const float* __restrict__ x, const float* __restrict__ params,
           float* __restrict__ out) {
    const int warp = (int)((blockIdx.x * blockDim.x + threadIdx.x) >> 5); // sample id
    const int lane = (int)(threadIdx.x & 31);
    if (warp >= BATCH) return;

    // ---- encoding: product state, computed analytically (all real) ----
    float c[NQ], s[NQ];
#pragma unroll
    for (int q = 0; q < NQ; ++q) {
        float h = 0.5f * __ldg(x + warp * NQ + q);
        __sincosf(h, &s[q], &c[q]);
    }

    // lane factor: lane bit j corresponds to qubit (4 - j)
    float lf = 1.0f;
#pragma unroll
    for (int j = 0; j < 5; ++j)
        lf *= ((lane >> j) & 1) ? s[4 - j] : c[4 - j];

    float ar[32], ai[32];
#pragma unroll
    for (int k = 0; k < 32; ++k) {
        // register bit j corresponds to qubit (9 - j); k bits are compile-time here
        float kf = lf;
#pragma unroll
        for (int j = 0; j < 5; ++j)
            kf *= ((k >> j) & 1) ? s[9 - j] : c[9 - j];
        ar[k] = kf;
        ai[k] = 0.0f;
    }

    // ---- variational layers (rolled loop: keep I$ footprint small) ----
#pragma unroll 1
    for (int l = 0; l < NL; ++l) {
        const float* p = params + l * (2 * NQ);
        apply_ryrz<0>(ar, ai, p, lane);
        apply_ryrz<1>(ar, ai, p, lane);
        apply_ryrz<2>(ar, ai, p, lane);
        apply_ryrz<3>(ar, ai, p, lane);
        apply_ryrz<4>(ar, ai, p, lane);
        apply_ryrz<5>(ar, ai, p, lane);
        apply_ryrz<6>(ar, ai, p, lane);
        apply_ryrz<7>(ar, ai, p, lane);
        apply_ryrz<8>(ar, ai, p, lane);
        apply_ryrz<9>(ar, ai, p, lane);
        apply_cnot<0>(ar, ai, lane);
        apply_cnot<1>(ar, ai, lane);
        apply_cnot<2>(ar, ai, lane);
        apply_cnot<3>(ar, ai, lane);
        apply_cnot<4>(ar, ai, lane);
        apply_cnot<5>(ar, ai, lane);
        apply_cnot<6>(ar, ai, lane);
        apply_cnot<7>(ar, ai, lane);
        apply_cnot<8>(ar, ai, lane);
        apply_cnot<9>(ar, ai, lane);
    }

    // ---- measurement: probs and per-qubit signed sums ----
    float psum = 0.0f;
    float sreg[5] = {0.0f, 0.0f, 0.0f, 0.0f, 0.0f};
#pragma unroll
    for (int k = 0; k < 32; ++k) {
        float p = fmaf(ar[k], ar[k], ai[k] * ai[k]);
        psum += p;
#pragma unroll
        for (int j = 0; j < 5; ++j)          // register bit j -> qubit (9 - j); sign folded at compile time
            sreg[j] += ((k >> j) & 1) ? -p : p;
    }

    float resv[NQ];
#pragma unroll
    for (int q = 0; q < 5; ++q) {            // qubit q (0..4) -> lane bit (4 - q)
        float v = ((lane >> (4 - q)) & 1) ? -psum : psum;
#pragma unroll
        for (int o = 16; o > 0; o >>= 1) v += __shfl_xor_sync(FULL, v, o);
        resv[q] = v;
    }
#pragma unroll
    for (int q = 5; q < NQ; ++q) {           // qubit q (5..9) -> register bit (9 - q)
        float v = sreg[9 - q];
#pragma unroll
        for (int o = 16; o > 0; o >>= 1) v += __shfl_xor_sync(FULL, v, o);
        resv[q] = v;
    }

    if (lane == 0) {
#pragma unroll
        for (int q = 0; q < NQ; ++q)
            out[warp * NQ + q] = resv[q];
    }
}

extern "C" void kernel_launch(void* const* d_in, const int* in_sizes, int n_in,
                              void* d_out, int out_size) {
    const float* x      = (const float*)d_in[0];   // [4096, 10] float32
    const float* params = (const float*)d_in[1];   // [4, 20] float32
    float* out          = (float*)d_out;           // [4096, 10] float32
    (void)in_sizes; (void)n_in; (void)out_size;
    pqc_kernel<<<BATCH / 8, 256>>>(x, params, out);
}

// round 6
// speedup vs baseline: 1.1213x; 1.1213x over previous
#include <cuda_runtime.h>

#define NQ 10
#define NL 4
#define BATCH 4096
#define FULL 0xFFFFFFFFu

typedef unsigned long long u64;

// ---- f32x2 packed-math primitives (sm_100+/sm_103a) ----
__device__ __forceinline__ u64 pk2(float lo, float hi) {
    u64 r; asm("mov.b64 %0,{%1,%2};" : "=l"(r) : "f"(lo), "f"(hi)); return r;
}
__device__ __forceinline__ void upk2(u64 a, float& lo, float& hi) {
    asm("mov.b64 {%0,%1},%2;" : "=f"(lo), "=f"(hi) : "l"(a));
}
__device__ __forceinline__ u64 fma2(u64 a, u64 b, u64 c) {
    u64 r; asm("fma.rn.f32x2 %0,%1,%2,%3;" : "=l"(r) : "l"(a), "l"(b), "l"(c)); return r;
}
__device__ __forceinline__ u64 mul2(u64 a, u64 b) {
    u64 r; asm("mul.rn.f32x2 %0,%1,%2;" : "=l"(r) : "l"(a), "l"(b)); return r;
}
__device__ __forceinline__ u64 swp2(u64 a) {           // swap the two f32 halves
    float x, y; upk2(a, x, y); return pk2(y, x);
}
__device__ __forceinline__ u64 shflx2(u64 a, int m) {  // 64-bit shfl_xor as 2x 32-bit
    float x, y; upk2(a, x, y);
    x = __shfl_xor_sync(FULL, x, m);
    y = __shfl_xor_sync(FULL, y, m);
    return pk2(x, y);
}
__device__ __forceinline__ u64 shfli2(u64 a, int src) {
    float x, y; upk2(a, x, y);
    x = __shfl_sync(FULL, x, src);
    y = __shfl_sync(FULL, y, src);
    return pk2(x, y);
}

// State layout: global amplitude index idx = (lane << 5) | (j << 1) | h, j = 0..15, h = 0/1.
//   qubit 0..4  -> lane bit (4 - q)
//   qubit 5..8  -> j bit    (8 - q)
//   qubit 9     -> packed half h (lo = 0, hi = 1)

// ---- fused RY+RZ on a j-bit qubit (q5..q8), fully packed ----
template<int JB>
__device__ __forceinline__ void ryrz_j(u64 (&Pr)[16], u64 (&Pi)[16],
                                       u64 cyv, u64 syv, u64 nsyv,
                                       u64 czv, u64 szv, u64 nszv) {
#pragma unroll
    for (int j0 = 0; j0 < 16; ++j0) {
        if (j0 & (1 << JB)) continue;
        const int j1 = j0 | (1 << JB);
        u64 t0r = fma2(cyv, Pr[j0], mul2(nsyv, Pr[j1]));
        u64 t0i = fma2(cyv, Pi[j0], mul2(nsyv, Pi[j1]));
        u64 t1r = fma2(syv, Pr[j0], mul2(cyv, Pr[j1]));
        u64 t1i = fma2(syv, Pi[j0], mul2(cyv, Pi[j1]));
        Pr[j0] = fma2(czv, t0r, mul2(szv,  t0i));
        Pi[j0] = fma2(czv, t0i, mul2(nszv, t0r));
        Pr[j1] = fma2(czv, t1r, mul2(nszv, t1i));
        Pi[j1] = fma2(czv, t1i, mul2(szv,  t1r));
    }
}

// ---- fused RY+RZ on qubit 9 (the packed dimension) ----
__device__ __forceinline__ void ryrz_pk(u64 (&Pr)[16], u64 (&Pi)[16],
                                        u64 cyv, float sy, float sz, u64 czv) {
    const u64 svec  = pk2(-sy,  sy);   // RY partner-term sign per half
    const u64 szpk  = pk2( sz, -sz);   // RZ re-update coefficient per half
    const u64 szpkn = pk2(-sz,  sz);   // RZ im-update coefficient per half
#pragma unroll
    for (int j = 0; j < 16; ++j) {
        u64 sr = swp2(Pr[j]);
        u64 si = swp2(Pi[j]);
        u64 tr = fma2(cyv, Pr[j], mul2(svec, sr));
        u64 ti = fma2(cyv, Pi[j], mul2(svec, si));
        Pr[j] = fma2(czv, tr, mul2(szpk,  ti));
        Pi[j] = fma2(czv, ti, mul2(szpkn, tr));
    }
}

// ---- fused RY+RZ on a lane-bit qubit (q0..q4), packed FMAs + 32-bit shuffles ----
template<int LB>
__device__ __forceinline__ void ryrz_lane(u64 (&Pr)[16], u64 (&Pi)[16],
                                          float cy, float sy, float cz, float sz,
                                          int lane) {
    const int m = 1 << LB;
    const bool hi = (lane & m) != 0;
    const float ss = hi ?  sy : -sy;
    const float pz = hi ?  sz : -sz;
    const u64 cyv = pk2(cy, cy), ssv = pk2(ss, ss);
    const u64 czv = pk2(cz, cz), pzv = pk2(pz, pz), npzv = pk2(-pz, -pz);
#pragma unroll
    for (int j = 0; j < 16; ++j) {
        u64 prv = shflx2(Pr[j], m);
        u64 piv = shflx2(Pi[j], m);
        u64 tr = fma2(cyv, Pr[j], mul2(ssv, prv));
        u64 ti = fma2(cyv, Pi[j], mul2(ssv, piv));
        Pr[j] = fma2(czv, tr, mul2(npzv, ti));
        Pi[j] = fma2(czv, ti, mul2(pzv,  tr));
    }
}

// ---- CNOT variants ----
template<int LC, int LT>   // lane control, lane target
__device__ __forceinline__ void cnot_ll(u64 (&Pr)[16], u64 (&Pi)[16], int lane) {
    const int src = (lane & (1 << LC)) ? (lane ^ (1 << LT)) : lane;
#pragma unroll
    for (int j = 0; j < 16; ++j) {
        Pr[j] = shfli2(Pr[j], src);
        Pi[j] = shfli2(Pi[j], src);
    }
}

__device__ __forceinline__ void cnot_lj_c4(u64 (&Pr)[16], u64 (&Pi)[16], int lane) {
    // control qubit 4 (lane bit 0), target qubit 5 (j bit 3)
    if (lane & 1) {
#pragma unroll
        for (int j = 0; j < 8; ++j) {
            u64 t = Pr[j]; Pr[j] = Pr[j | 8]; Pr[j | 8] = t;
            u64 u = Pi[j]; Pi[j] = Pi[j | 8]; Pi[j | 8] = u;
        }
    }
}

template<int JC, int JT>   // both j bits: compile-time register renames
__device__ __forceinline__ void cnot_jj(u64 (&Pr)[16], u64 (&Pi)[16]) {
#pragma unroll
    for (int j = 0; j < 16; ++j) {
        if ((j & (1 << JC)) && !(j & (1 << JT))) {
            const int j1 = j | (1 << JT);
            u64 t = Pr[j]; Pr[j] = Pr[j1]; Pr[j1] = t;
            u64 u = Pi[j]; Pi[j] = Pi[j1]; Pi[j1] = u;
        }
    }
}

__device__ __forceinline__ void cnot_jp_c8(u64 (&Pr)[16], u64 (&Pi)[16]) {
    // control qubit 8 (j bit 0), target qubit 9 (packed half): swap halves for odd j
#pragma unroll
    for (int j = 1; j < 16; j += 2) {
        Pr[j] = swp2(Pr[j]);
        Pi[j] = swp2(Pi[j]);
    }
}

__device__ __forceinline__ void cnot_pl_c9(u64 (&Pr)[16], u64 (&Pi)[16]) {
    // control qubit 9 (hi half), target qubit 0 (lane bit 4): shuffle hi halves only
#pragma unroll
    for (int j = 0; j < 16; ++j) {
        float x, y; upk2(Pr[j], x, y);
        y = __shfl_xor_sync(FULL, y, 16);
        Pr[j] = pk2(x, y);
        float u, v; upk2(Pi[j], u, v);
        v = __shfl_xor_sync(FULL, v, 16);
        Pi[j] = pk2(u, v);
    }
}

// ---- dispatch ----
template<int Q>
__device__ __forceinline__ void apply_ryrz(u64 (&Pr)[16], u64 (&Pi)[16],
                                           const float* __restrict__ p, int lane) {
    const float hy = 0.5f * __ldg(p + Q);
    const float hz = 0.5f * __ldg(p + NQ + Q);
    float cy, sy, cz, sz;
    __sincosf(hy, &sy, &cy);
    __sincosf(hz, &sz, &cz);
    if constexpr (Q <= 4) {
        ryrz_lane<4 - Q>(Pr, Pi, cy, sy, cz, sz, lane);
    } else if constexpr (Q <= 8) {
        const u64 cyv = pk2(cy, cy), syv = pk2(sy, sy), nsyv = pk2(-sy, -sy);
        const u64 czv = pk2(cz, cz), szv = pk2(sz, sz), nszv = pk2(-sz, -sz);
        ryrz_j<8 - Q>(Pr, Pi, cyv, syv, nsyv, czv, szv, nszv);
    } else {
        ryrz_pk(Pr, Pi, pk2(cy, cy), sy, sz, pk2(cz, cz));
    }
}

template<int C>
__device__ __forceinline__ void apply_cnot(u64 (&Pr)[16], u64 (&Pi)[16], int lane) {
    if constexpr (C <= 3)      cnot_ll<4 - C, 3 - C>(Pr, Pi, lane);
    else if constexpr (C == 4) cnot_lj_c4(Pr, Pi, lane);
    else if constexpr (C <= 7) cnot_jj<8 - C, 7 - C>(Pr, Pi);
    else if constexpr (C == 8) cnot_jp_c8(Pr, Pi);
    else                       cnot_pl_c9(Pr, Pi);
}

__global__ void __launch_bounds__(256)
pqc_kernel(const float* __restrict__ x, const float* __restrict__ params,
           float* __restrict__ out) {
    const int warp = (int)((blockIdx.x * blockDim.x + threadIdx.x) >> 5);
    const int lane = (int)(threadIdx.x & 31);
    if (warp >= BATCH) return;

    // ---- encoding: analytic product state (all real) ----
    float c[NQ], s[NQ];
#pragma unroll
    for (int q = 0; q < NQ; ++q) {
        float h = 0.5f * __ldg(x + warp * NQ + q);
        __sincosf(h, &s[q], &c[q]);
    }

    float lf = 1.0f;                   // lane bit L -> qubit (4 - L)
#pragma unroll
    for (int L = 0; L < 5; ++L)
        lf *= ((lane >> L) & 1) ? s[4 - L] : c[4 - L];

    u64 Pr[16], Pi[16];
#pragma unroll
    for (int j = 0; j < 16; ++j) {
        float f = lf;                  // j bit JB -> qubit (8 - JB)
#pragma unroll
        for (int JB = 0; JB < 4; ++JB)
            f *= ((j >> JB) & 1) ? s[8 - JB] : c[8 - JB];
        Pr[j] = pk2(f * c[9], f * s[9]);   // packed half -> qubit 9
        Pi[j] = pk2(0.0f, 0.0f);
    }

    // ---- variational layers ----
#pragma unroll 1
    for (int l = 0; l < NL; ++l) {
        const float* p = params + l * (2 * NQ);
        apply_ryrz<0>(Pr, Pi, p, lane);
        apply_ryrz<1>(Pr, Pi, p, lane);
        apply_ryrz<2>(Pr, Pi, p, lane);
        apply_ryrz<3>(Pr, Pi, p, lane);
        apply_ryrz<4>(Pr, Pi, p, lane);
        apply_ryrz<5>(Pr, Pi, p, lane);
        apply_ryrz<6>(Pr, Pi, p, lane);
        apply_ryrz<7>(Pr, Pi, p, lane);
        apply_ryrz<8>(Pr, Pi, p, lane);
        apply_ryrz<9>(Pr, Pi, p, lane);
        apply_cnot<0>(Pr, Pi, lane);
        apply_cnot<1>(Pr, Pi, lane);
        apply_cnot<2>(Pr, Pi, lane);
        apply_cnot<3>(Pr, Pi, lane);
        apply_cnot<4>(Pr, Pi, lane);
        apply_cnot<5>(Pr, Pi, lane);
        apply_cnot<6>(Pr, Pi, lane);
        apply_cnot<7>(Pr, Pi, lane);
        apply_cnot<8>(Pr, Pi, lane);
        apply_cnot<9>(Pr, Pi, lane);
    }

    // ---- measurement ----
    float psum = 0.0f, s9 = 0.0f;
    float sj[4] = {0.0f, 0.0f, 0.0f, 0.0f};
#pragma unroll
    for (int j = 0; j < 16; ++j) {
        u64 pp = fma2(Pr[j], Pr[j], mul2(Pi[j], Pi[j]));
        float plo, phi; upk2(pp, plo, phi);
        float tot = plo + phi;
        psum += tot;
        s9   += plo - phi;                       // qubit 9: lo(+) / hi(-)
        sj[0] += (j & 1) ? -tot : tot;           // j bit 0 -> qubit 8
        sj[1] += (j & 2) ? -tot : tot;           // j bit 1 -> qubit 7
        sj[2] += (j & 4) ? -tot : tot;           // j bit 2 -> qubit 6
        sj[3] += (j & 8) ? -tot : tot;           // j bit 3 -> qubit 5
    }

    float resv[NQ];
#pragma unroll
    for (int q = 0; q < 5; ++q) {                // qubit q -> lane bit (4 - q)
        float v = ((lane >> (4 - q)) & 1) ? -psum : psum;
#pragma unroll
        for (int o = 16; o > 0; o >>= 1) v += __shfl_xor_sync(FULL, v, o);
        resv[q] = v;
    }
#pragma unroll
    for (int q = 5; q < 9; ++q) {                // qubit q -> j bit (8 - q)
        float v = sj[8 - q];
#pragma unroll
        for (int o = 16; o > 0; o >>= 1) v += __shfl_xor_sync(FULL, v, o);
        resv[q] = v;
    }
    {
        float v = s9;
#pragma unroll
        for (int o = 16; o > 0; o >>= 1) v += __shfl_xor_sync(FULL, v, o);
        resv[9] = v;
    }

    if (lane == 0) {
#pragma unroll
        for (int q = 0; q < NQ; ++q)
            out[warp * NQ + q] = resv[q];
    }
}

extern "C" void kernel_launch(void* const* d_in, const int* in_sizes, int n_in,
                              void* d_out, int out_size) {
    const float* x      = (const float*)d_in[0];   // [4096, 10] float32
    const float* params = (const float*)d_in[1];   // [4, 20] float32
    float* out          = (float*)d_out;           // [4096, 10] float32
    (void)in_sizes; (void)n_in; (void)out_size;
    pqc_kernel<<<BATCH / 8, 256>>>(x, params, out);
}

// round 7
// speedup vs baseline: 1.8237x; 1.6264x over previous
#include <cuda_runtime.h>

#define NQ 10
#define NL 4
#define BATCH 4096
#define FULL 0xFFFFFFFFu

typedef unsigned long long u64;

// ---- f32x2 packed-math primitives (sm_100+/sm_103a) ----
__device__ __forceinline__ u64 pk2(float lo, float hi) {
    u64 r; asm("mov.b64 %0,{%1,%2};" : "=l"(r) : "f"(lo), "f"(hi)); return r;
}
__device__ __forceinline__ void upk2(u64 a, float& lo, float& hi) {
    asm("mov.b64 {%0,%1},%2;" : "=f"(lo), "=f"(hi) : "l"(a));
}
__device__ __forceinline__ u64 fma2(u64 a, u64 b, u64 c) {
    u64 r; asm("fma.rn.f32x2 %0,%1,%2,%3;" : "=l"(r) : "l"(a), "l"(b), "l"(c)); return r;
}
__device__ __forceinline__ u64 mul2(u64 a, u64 b) {
    u64 r; asm("mul.rn.f32x2 %0,%1,%2;" : "=l"(r) : "l"(a), "l"(b)); return r;
}
__device__ __forceinline__ u64 swp2(u64 a) {           // swap the two f32 halves
    float x, y; upk2(a, x, y); return pk2(y, x);
}
__device__ __forceinline__ u64 shflx2(u64 a, int m) {
    float x, y; upk2(a, x, y);
    x = __shfl_xor_sync(FULL, x, m);
    y = __shfl_xor_sync(FULL, y, m);
    return pk2(x, y);
}
__device__ __forceinline__ u64 shfli2(u64 a, int src) {
    float x, y; upk2(a, x, y);
    x = __shfl_sync(FULL, x, src);
    y = __shfl_sync(FULL, y, src);
    return pk2(x, y);
}

// State layout: amplitude index idx = (lane << 5) | (j << 1) | h, j = 0..15, h = 0/1.
//   qubit 0..4  -> lane bit (4 - q)
//   qubit 5..8  -> j bit    (8 - q)
//   qubit 9     -> packed half h (lo = 0, hi = 1)

// ---- fused RY (+optional RZ) on a j-bit qubit (q5..q8) ----
template<int JB, bool RZ>
__device__ __forceinline__ void ryrz_j(u64 (&Pr)[16], u64 (&Pi)[16],
                                       u64 cyv, u64 syv, u64 nsyv,
                                       u64 czv, u64 szv, u64 nszv) {
#pragma unroll
    for (int j0 = 0; j0 < 16; ++j0) {
        if (j0 & (1 << JB)) continue;
        const int j1 = j0 | (1 << JB);
        u64 t0r = fma2(cyv, Pr[j0], mul2(nsyv, Pr[j1]));
        u64 t0i = fma2(cyv, Pi[j0], mul2(nsyv, Pi[j1]));
        u64 t1r = fma2(syv, Pr[j0], mul2(cyv, Pr[j1]));
        u64 t1i = fma2(syv, Pi[j0], mul2(cyv, Pi[j1]));
        if constexpr (RZ) {
            Pr[j0] = fma2(czv, t0r, mul2(szv,  t0i));
            Pi[j0] = fma2(czv, t0i, mul2(nszv, t0r));
            Pr[j1] = fma2(czv, t1r, mul2(nszv, t1i));
            Pi[j1] = fma2(czv, t1i, mul2(szv,  t1r));
        } else {
            Pr[j0] = t0r; Pi[j0] = t0i;
            Pr[j1] = t1r; Pi[j1] = t1i;
        }
    }
}

// ---- fused RY (+optional RZ) on qubit 9 (the packed dimension) ----
template<bool RZ>
__device__ __forceinline__ void ryrz_pk(u64 (&Pr)[16], u64 (&Pi)[16],
                                        u64 cyv, float sy, float sz, u64 czv) {
    const u64 svec  = pk2(-sy,  sy);
    const u64 szpk  = pk2( sz, -sz);
    const u64 szpkn = pk2(-sz,  sz);
#pragma unroll
    for (int j = 0; j < 16; ++j) {
        u64 sr = swp2(Pr[j]);
        u64 si = swp2(Pi[j]);
        u64 tr = fma2(cyv, Pr[j], mul2(svec, sr));
        u64 ti = fma2(cyv, Pi[j], mul2(svec, si));
        if constexpr (RZ) {
            Pr[j] = fma2(czv, tr, mul2(szpk,  ti));
            Pi[j] = fma2(czv, ti, mul2(szpkn, tr));
        } else {
            Pr[j] = tr; Pi[j] = ti;
        }
    }
}

// ---- fused RY (+optional RZ) on a lane-bit qubit (q0..q4) ----
template<int LB, bool RZ>
__device__ __forceinline__ void ryrz_lane(u64 (&Pr)[16], u64 (&Pi)[16],
                                          float cy, float sy, float cz, float sz,
                                          int lane) {
    const int m = 1 << LB;
    const bool hi = (lane & m) != 0;
    const float ss = hi ?  sy : -sy;
    const float pz = hi ?  sz : -sz;
    const u64 cyv = pk2(cy, cy), ssv = pk2(ss, ss);
    const u64 czv = pk2(cz, cz), pzv = pk2(pz, pz), npzv = pk2(-pz, -pz);
#pragma unroll
    for (int j = 0; j < 16; ++j) {
        u64 prv = shflx2(Pr[j], m);
        u64 piv = shflx2(Pi[j], m);
        u64 tr = fma2(cyv, Pr[j], mul2(ssv, prv));
        u64 ti = fma2(cyv, Pi[j], mul2(ssv, piv));
        if constexpr (RZ) {
            Pr[j] = fma2(czv, tr, mul2(npzv, ti));
            Pi[j] = fma2(czv, ti, mul2(pzv,  tr));
        } else {
            Pr[j] = tr; Pi[j] = ti;
        }
    }
}

// ---- composed CNOT(0,1)(1,2)(2,3)(3,4): single lane permutation ----
__device__ __forceinline__ void cnot_lane_ring(u64 (&Pr)[16], u64 (&Pi)[16], int lane) {
    const int src = lane ^ ((lane >> 1) & 0xF);
#pragma unroll
    for (int j = 0; j < 16; ++j) {
        Pr[j] = shfli2(Pr[j], src);
        Pi[j] = shfli2(Pi[j], src);
    }
}

__device__ __forceinline__ void cnot_lj_c4(u64 (&Pr)[16], u64 (&Pi)[16], int lane) {
    // control qubit 4 (lane bit 0), target qubit 5 (j bit 3)
    if (lane & 1) {
#pragma unroll
        for (int j = 0; j < 8; ++j) {
            u64 t = Pr[j]; Pr[j] = Pr[j | 8]; Pr[j | 8] = t;
            u64 u = Pi[j]; Pi[j] = Pi[j | 8]; Pi[j | 8] = u;
        }
    }
}

template<int JC, int JT>
__device__ __forceinline__ void cnot_jj(u64 (&Pr)[16], u64 (&Pi)[16]) {
#pragma unroll
    for (int j = 0; j < 16; ++j) {
        if ((j & (1 << JC)) && !(j & (1 << JT))) {
            const int j1 = j | (1 << JT);
            u64 t = Pr[j]; Pr[j] = Pr[j1]; Pr[j1] = t;
            u64 u = Pi[j]; Pi[j] = Pi[j1]; Pi[j1] = u;
        }
    }
}

__device__ __forceinline__ void cnot_jp_c8(u64 (&Pr)[16], u64 (&Pi)[16]) {
    // control qubit 8 (j bit 0), target qubit 9 (packed half)
#pragma unroll
    for (int j = 1; j < 16; j += 2) {
        Pr[j] = swp2(Pr[j]);
        Pi[j] = swp2(Pi[j]);
    }
}

__device__ __forceinline__ void cnot_pl_c9(u64 (&Pr)[16], u64 (&Pi)[16]) {
    // control qubit 9 (hi half), target qubit 0 (lane bit 4)
#pragma unroll
    for (int j = 0; j < 16; ++j) {
        float x, y; upk2(Pr[j], x, y);
        y = __shfl_xor_sync(FULL, y, 16);
        Pr[j] = pk2(x, y);
        float u, v; upk2(Pi[j], u, v);
        v = __shfl_xor_sync(FULL, v, 16);
        Pi[j] = pk2(u, v);
    }
}

// ---- one gate layer's rotations (optionally with RZ) ----
template<int Q, bool RZ>
__device__ __forceinline__ void apply_ryrz(u64 (&Pr)[16], u64 (&Pi)[16],
                                           const float* __restrict__ p, int lane) {
    const float hy = 0.5f * __ldg(p + Q);
    const float hz = 0.5f * __ldg(p + NQ + Q);
    float cy, sy, cz, sz;
    __sincosf(hy, &sy, &cy);
    __sincosf(hz, &sz, &cz);
    if constexpr (Q <= 4) {
        ryrz_lane<4 - Q, RZ>(Pr, Pi, cy, sy, cz, sz, lane);
    } else if constexpr (Q <= 8) {
        const u64 cyv = pk2(cy, cy), syv = pk2(sy, sy), nsyv = pk2(-sy, -sy);
        const u64 czv = pk2(cz, cz), szv = pk2(sz, sz), nszv = pk2(-sz, -sz);
        ryrz_j<8 - Q, RZ>(Pr, Pi, cyv, syv, nsyv, czv, szv, nszv);
    } else {
        ryrz_pk<RZ>(Pr, Pi, pk2(cy, cy), sy, sz, pk2(cz, cz));
    }
}

template<bool RZ>
__device__ __forceinline__ void layer_rotations(u64 (&Pr)[16], u64 (&Pi)[16],
                                                const float* __restrict__ p, int lane) {
    apply_ryrz<0, RZ>(Pr, Pi, p, lane);
    apply_ryrz<1, RZ>(Pr, Pi, p, lane);
    apply_ryrz<2, RZ>(Pr, Pi, p, lane);
    apply_ryrz<3, RZ>(Pr, Pi, p, lane);
    apply_ryrz<4, RZ>(Pr, Pi, p, lane);
    apply_ryrz<5, RZ>(Pr, Pi, p, lane);
    apply_ryrz<6, RZ>(Pr, Pi, p, lane);
    apply_ryrz<7, RZ>(Pr, Pi, p, lane);
    apply_ryrz<8, RZ>(Pr, Pi, p, lane);
    apply_ryrz<9, RZ>(Pr, Pi, p, lane);
}

__device__ __forceinline__ void layer_cnots(u64 (&Pr)[16], u64 (&Pi)[16], int lane) {
    cnot_lane_ring(Pr, Pi, lane);   // CNOT(0,1)(1,2)(2,3)(3,4) composed
    cnot_lj_c4(Pr, Pi, lane);       // CNOT(4,5)
    cnot_jj<3, 2>(Pr, Pi);          // CNOT(5,6)
    cnot_jj<2, 1>(Pr, Pi);          // CNOT(6,7)
    cnot_jj<1, 0>(Pr, Pi);          // CNOT(7,8)
    cnot_jp_c8(Pr, Pi);             // CNOT(8,9)
    cnot_pl_c9(Pr, Pi);             // CNOT(9,0)
}

__global__ void __launch_bounds__(256)
pqc_kernel(const float* __restrict__ x, const float* __restrict__ params,
           float* __restrict__ out) {
    const int warp = (int)((blockIdx.x * blockDim.x + threadIdx.x) >> 5);
    const int lane = (int)(threadIdx.x & 31);
    if (warp >= BATCH) return;

    // ======== init: encoding RY(x) fused with layer-0 RY(θy) and RZ(θz) ========
    // state = product over qubits of RY(x_q + θy_q)|0>, with analytic RZ phases.
    float c[NQ], s[NQ], tz[NQ];
#pragma unroll
    for (int q = 0; q < NQ; ++q) {
        float hy = 0.5f * (__ldg(x + warp * NQ + q) + __ldg(params + q));
        __sincosf(hy, &s[q], &c[q]);
        tz[q] = 0.5f * __ldg(params + NQ + q);
    }

    float lf = 1.0f, phL = 0.0f;          // lane bit L -> qubit (4 - L)
#pragma unroll
    for (int L = 0; L < 5; ++L) {
        const int q = 4 - L;
        if ((lane >> L) & 1) { lf *= s[q]; phL += tz[q]; }
        else                 { lf *= c[q]; phL -= tz[q]; }
    }

    float c9z, s9z;
    __sincosf(tz[9], &s9z, &c9z);

    u64 Pr[16], Pi[16];
#pragma unroll
    for (int j = 0; j < 16; ++j) {
        float f = lf, ph = phL;           // j bit JB -> qubit (8 - JB)
#pragma unroll
        for (int JB = 0; JB < 4; ++JB) {
            const int q = 8 - JB;
            if ((j >> JB) & 1) { f *= s[q]; ph += tz[q]; }
            else               { f *= c[q]; ph -= tz[q]; }
        }
        float cp, sp;
        __sincosf(ph, &sp, &cp);
        // h=0: phase (ph - tz9), magnitude f*c9 ; h=1: phase (ph + tz9), magnitude f*s9
        const float re0 = fmaf(cp, c9z,  sp * s9z);
        const float im0 = fmaf(sp, c9z, -(cp * s9z));
        const float re1 = fmaf(cp, c9z, -(sp * s9z));
        const float im1 = fmaf(sp, c9z,  cp * s9z);
        const float f0 = f * c[9], f1 = f * s[9];
        Pr[j] = pk2(f0 * re0, f1 * re1);
        Pi[j] = pk2(f0 * im0, f1 * im1);
    }
    // layer 0's CNOT ring still applies:
    layer_cnots(Pr, Pi, lane);

    // ======== middle layers (full rotations + CNOT ring) ========
#pragma unroll 1
    for (int l = 1; l < NL - 1; ++l) {
        const float* p = params + l * (2 * NQ);
        layer_rotations<true>(Pr, Pi, p, lane);
        layer_cnots(Pr, Pi, lane);
    }

    // ======== last layer: RY only (RZ is phase-only), NO CNOTs (folded into signs) ========
    layer_rotations<false>(Pr, Pi, params + (NL - 1) * (2 * NQ), lane);

    // ======== measurement with CNOT-ring permutation folded into sign parities ========
    // final bit q:  b'_0 = parity(b1..b9);  b'_q = parity(b0..b_q) for q>=1
    float psum = 0.0f, A = 0.0f;
    float S5 = 0.0f, S6 = 0.0f, S7 = 0.0f, S8 = 0.0f;
#pragma unroll
    for (int j = 0; j < 16; ++j) {
        u64 pp = fma2(Pr[j], Pr[j], mul2(Pi[j], Pi[j]));
        float plo, phi; upk2(pp, plo, phi);
        const float T = plo + phi;        // h-sum
        const float D = plo - phi;        // (-1)^h weighted
        psum += T;
        A  += (__popc(j)      & 1) ? -D : D;   // jparity ^ h weighting
        S5 += ((j >> 3)       & 1) ? -T : T;   // parity of j bit 3         (q5)
        S6 += (__popc(j >> 2) & 1) ? -T : T;   // parity of j bits 3..2     (q6)
        S7 += (__popc(j >> 1) & 1) ? -T : T;   // parity of j bits 3..1     (q7)
        S8 += (__popc(j)      & 1) ? -T : T;   // parity of j bits 3..0     (q8)
    }

    const int lp = __popc(lane) & 1;      // parity of qubits 0..4
    float resv[NQ];
    resv[0] = ((lp ^ (lane >> 4)) & 1) ? -A : A;        // parity(b1..b9)
    resv[1] = (__popc(lane >> 3) & 1) ? -psum : psum;   // parity(b0..b1)
    resv[2] = (__popc(lane >> 2) & 1) ? -psum : psum;
    resv[3] = (__popc(lane >> 1) & 1) ? -psum : psum;
    resv[4] = lp ? -psum : psum;
    resv[5] = lp ? -S5 : S5;
    resv[6] = lp ? -S6 : S6;
    resv[7] = lp ? -S7 : S7;
    resv[8] = lp ? -S8 : S8;
    resv[9] = lp ? -A  : A;

#pragma unroll
    for (int q = 0; q < NQ; ++q) {
        float v = resv[q];
#pragma unroll
        for (int o = 16; o > 0; o >>= 1) v += __shfl_xor_sync(FULL, v, o);
        resv[q] = v;
    }

    if (lane == 0) {
#pragma unroll
        for (int q = 0; q < NQ; ++q)
            out[warp * NQ + q] = resv[q];
    }
}

extern "C" void kernel_launch(void* const* d_in, const int* in_sizes, int n_in,
                              void* d_out, int out_size) {
    const float* x      = (const float*)d_in[0];   // [4096, 10] float32
    const float* params = (const float*)d_in[1];   // [4, 20] float32
    float* out          = (float*)d_out;           // [4096, 10] float32
    (void)in_sizes; (void)n_in; (void)out_size;
    pqc_kernel<<<BATCH / 8, 256>>>(x, params, out);
}